// round 6
// baseline (speedup 1.0000x reference)
#include <cuda_runtime.h>
#include <cstdint>

// Problem constants
#define Bc    2
#define Nc    128
#define Sc    4
#define DGc   8
#define CINc  4
#define COUTc 8
#define HIDc  32

// Dynamic smem layout (float offsets).
#define KYW1d 0        // dup [c][k2][o][2]  512
#define KGW1d 512      // dup [c][k8][o][2]  2048
#define KYB1d 2560     // dup [c][o][2]      256
#define KGB1d 2816     // dup                256
#define KYW2t 3072     // non-dup [c][k][o]  4096
#define KGW2t 7168     //                    4096
#define KYB2o 11264    // natural [c][o]     128
#define KGB2o 11392    //                    128
#define KYW3o 11520    //                    128
#define KGW3o 11648    //                    128
#define KYB3o 11776    // 4
#define KGB3o 11780    // 4
#define WOUTo 11784    // 32
#define SREDo 11816    // 64
#define SWTOT 11880
#define SMEM_BYTES (SWTOT * 4)

typedef unsigned long long u64;

__device__ __forceinline__ u64 pk2(float lo, float hi) {
    u64 r; asm("mov.b64 %0, {%1, %2};" : "=l"(r) : "f"(lo), "f"(hi)); return r;
}
__device__ __forceinline__ void upk2(u64 v, float& lo, float& hi) {
    asm("mov.b64 {%0, %1}, %2;" : "=f"(lo), "=f"(hi) : "l"(v));
}
__device__ __forceinline__ u64 fma2(u64 a, u64 b, u64 c) {
    u64 d; asm("fma.rn.f32x2 %0, %1, %2, %3;" : "=l"(d) : "l"(a), "l"(b), "l"(c)); return d;
}
__device__ __forceinline__ u64 mul2(u64 a, u64 b) {
    u64 d; asm("mul.rn.f32x2 %0, %1, %2;" : "=l"(d) : "l"(a), "l"(b)); return d;
}
__device__ __forceinline__ u64 add2(u64 a, u64 b) {
    u64 d; asm("add.rn.f32x2 %0, %1, %2;" : "=l"(d) : "l"(a), "l"(b)); return d;
}
__device__ __forceinline__ float ex2f(float x) {
    float r; asm("ex2.approx.f32 %0, %1;" : "=f"(r) : "f"(x)); return r;
}
__device__ __forceinline__ float rcpf(float x) {
    float r; asm("rcp.approx.f32 %0, %1;" : "=f"(r) : "f"(x)); return r;
}

#define LOG2E 1.4426950408889634f

__device__ __forceinline__ u64 silu2(u64 x2) {
    u64 t = mul2(x2, pk2(-LOG2E, -LOG2E));
    float t0, t1; upk2(t, t0, t1);
    u64 d = add2(pk2(ex2f(t0), ex2f(t1)), pk2(1.0f, 1.0f));
    float d0, d1; upk2(d, d0, d1);
    return mul2(x2, pk2(rcpf(d0), rcpf(d1)));
}
__device__ __forceinline__ float silu_f(float x) {
    float e = ex2f(-LOG2E * x);
    return x * rcpf(1.0f + e);
}

// Fused layers 2+3 with lazy silu on the layer-1 raw pre-activations.
// hp[] holds RAW pre-activations on entry; chunk 0 applies silu in place.
__device__ __forceinline__ void mlp23(u64* hp,
                                      const float* __restrict__ w2,
                                      const float* __restrict__ b2,
                                      const float* __restrict__ w3,
                                      float b3, float& kA, float& kB)
{
    u64 tA0 = pk2(0.f, 0.f), tA1 = pk2(0.f, 0.f);
    u64 tB0 = pk2(0.f, 0.f), tB1 = pk2(0.f, 0.f);

    #pragma unroll
    for (int ch = 0; ch < 2; ++ch) {
        u64 aA[8], aB[8];
        {
            const ulonglong2* bb = reinterpret_cast<const ulonglong2*>(b2 + ch*16);
            ulonglong2 b0 = bb[0], b1v = bb[1], b2v = bb[2], b3v = bb[3];
            aA[0]=b0.x;  aA[1]=b0.y;  aA[2]=b1v.x; aA[3]=b1v.y;
            aA[4]=b2v.x; aA[5]=b2v.y; aA[6]=b3v.x; aA[7]=b3v.y;
            aB[0]=b0.x;  aB[1]=b0.y;  aB[2]=b1v.x; aB[3]=b1v.y;
            aB[4]=b2v.x; aB[5]=b2v.y; aB[6]=b3v.x; aB[7]=b3v.y;
        }
        const float* wkb = w2 + ch*16;
        #pragma unroll
        for (int k = 0; k < HIDc; ++k) {
            u64 hk = hp[k];
            if (ch == 0) { hk = silu2(hk); hp[k] = hk; }   // lazy silu, mixed with fma
            float ha, hb; upk2(hk, ha, hb);
            const u64 hAd = pk2(ha, ha);
            const u64 hBd = pk2(hb, hb);
            const ulonglong2* wv = reinterpret_cast<const ulonglong2*>(wkb + k*32);
            ulonglong2 w0 = wv[0], w1v = wv[1], w2v = wv[2], w3v = wv[3];
            aA[0] = fma2(hAd, w0.x,  aA[0]);
            aA[1] = fma2(hAd, w0.y,  aA[1]);
            aA[2] = fma2(hAd, w1v.x, aA[2]);
            aA[3] = fma2(hAd, w1v.y, aA[3]);
            aA[4] = fma2(hAd, w2v.x, aA[4]);
            aA[5] = fma2(hAd, w2v.y, aA[5]);
            aA[6] = fma2(hAd, w3v.x, aA[6]);
            aA[7] = fma2(hAd, w3v.y, aA[7]);
            aB[0] = fma2(hBd, w0.x,  aB[0]);
            aB[1] = fma2(hBd, w0.y,  aB[1]);
            aB[2] = fma2(hBd, w1v.x, aB[2]);
            aB[3] = fma2(hBd, w1v.y, aB[3]);
            aB[4] = fma2(hBd, w2v.x, aB[4]);
            aB[5] = fma2(hBd, w2v.y, aB[5]);
            aB[6] = fma2(hBd, w3v.x, aB[6]);
            aB[7] = fma2(hBd, w3v.y, aB[7]);
        }
        // silu + fold into layer-3 dot; 4 independent chains
        const ulonglong2* w3p = reinterpret_cast<const ulonglong2*>(w3 + ch*16);
        ulonglong2 p0 = w3p[0], p1 = w3p[1], p2 = w3p[2], p3 = w3p[3];
        tA0 = fma2(silu2(aA[0]), p0.x, tA0);
        tB0 = fma2(silu2(aB[0]), p0.x, tB0);
        tA1 = fma2(silu2(aA[1]), p0.y, tA1);
        tB1 = fma2(silu2(aB[1]), p0.y, tB1);
        tA0 = fma2(silu2(aA[2]), p1.x, tA0);
        tB0 = fma2(silu2(aB[2]), p1.x, tB0);
        tA1 = fma2(silu2(aA[3]), p1.y, tA1);
        tB1 = fma2(silu2(aB[3]), p1.y, tB1);
        tA0 = fma2(silu2(aA[4]), p2.x, tA0);
        tB0 = fma2(silu2(aB[4]), p2.x, tB0);
        tA1 = fma2(silu2(aA[5]), p2.y, tA1);
        tB1 = fma2(silu2(aB[5]), p2.y, tB1);
        tA0 = fma2(silu2(aA[6]), p3.x, tA0);
        tB0 = fma2(silu2(aB[6]), p3.x, tB0);
        tA1 = fma2(silu2(aA[7]), p3.y, tA1);
        tB1 = fma2(silu2(aB[7]), p3.y, tB1);
    }
    float a0, a1, b0, b1v;
    upk2(add2(tA0, tA1), a0, a1);
    upk2(add2(tB0, tB1), b0, b1v);
    kA += silu_f(a0 + a1 + b3);
    kB += silu_f(b0 + b1v + b3);
}

__global__ __launch_bounds__(256, 2)
void ema_kernel(const float* __restrict__ g,
                const float* __restrict__ f,
                const int* __restrict__ mask,
                const float* __restrict__ kyW1, const float* __restrict__ kyb1,
                const float* __restrict__ kyW2, const float* __restrict__ kyb2,
                const float* __restrict__ kyW3, const float* __restrict__ kyb3,
                const float* __restrict__ kgW1, const float* __restrict__ kgb1,
                const float* __restrict__ kgW2, const float* __restrict__ kgb2,
                const float* __restrict__ kgW3, const float* __restrict__ kgb3,
                const float* __restrict__ wout,
                float* __restrict__ out)
{
    extern __shared__ __align__(16) float sw[];

    const int tid = threadIdx.x;

    // ---- decode query + issue all GMEM input loads BEFORE staging ----
    const int bid = blockIdx.x;
    const int b   = bid >> 9;
    const int rem = bid & 511;
    const int i   = rem >> 2;
    const int s   = rem & 3;

    const int j0 = tid >> 2;
    const int t  = tid & 3;
    const int j1 = j0 + 64;

    const float* fqp = f + (((size_t)b * Nc + i) * Sc + s) * CINc;
    float4 fqv = *reinterpret_cast<const float4*>(fqp);

    const float* gp = g + ((((((size_t)b * Nc + i) * Nc + j0) * Sc + s) * Sc) + t) * DGc;
    float4 g0 = *reinterpret_cast<const float4*>(gp);
    float4 g1 = *reinterpret_cast<const float4*>(gp + 4);
    const float* gp2 = gp + (size_t)64 * Sc * Sc * DGc;
    float4 h0 = *reinterpret_cast<const float4*>(gp2);
    float4 h1 = *reinterpret_cast<const float4*>(gp2 + 4);

    const int mkiA = mask[((size_t)b * Nc + j0) * Sc + t];
    const int mkiB = mask[((size_t)b * Nc + j1) * Sc + t];

    float4 fkAv = *reinterpret_cast<const float4*>(f + (((size_t)b * Nc + j0) * Sc + t) * CINc);
    float4 fkBv = *reinterpret_cast<const float4*>(f + (((size_t)b * Nc + j1) * Sc + t) * CINc);

    // ---- stage weights ----
    {
        for (int idx = tid; idx < 4096; idx += 256) {
            int c = idx >> 10, o = (idx >> 5) & 31, k = idx & 31;
            int d = c * 1024 + k * 32 + o;
            sw[KYW2t + d] = kyW2[idx];
            sw[KGW2t + d] = kgW2[idx];
        }
        for (int idx = tid; idx < 1024; idx += 256) {
            int c = idx >> 8, o = (idx >> 3) & 31, k = idx & 7;
            int d = ((c * 8 + k) * 32 + o) * 2;
            float v = kgW1[idx];
            sw[KGW1d + d] = v; sw[KGW1d + d + 1] = v;
        }
        {
            int idx = tid;
            int c = idx >> 6, o = (idx >> 1) & 31, k = idx & 1;
            int d = ((c * 2 + k) * 32 + o) * 2;
            float v = kyW1[idx];
            sw[KYW1d + d] = v; sw[KYW1d + d + 1] = v;
        }
        for (int idx = tid; idx < 128; idx += 256) {
            float v;
            v = kyb1[idx]; sw[KYB1d + 2*idx] = v; sw[KYB1d + 2*idx + 1] = v;
            v = kgb1[idx]; sw[KGB1d + 2*idx] = v; sw[KGB1d + 2*idx + 1] = v;
            sw[KYB2o + idx] = kyb2[idx];
            sw[KGB2o + idx] = kgb2[idx];
            sw[KYW3o + idx] = kyW3[idx];
            sw[KGW3o + idx] = kgW3[idx];
        }
        if (tid < 4) { sw[KYB3o + tid] = kyb3[tid]; sw[KGB3o + tid] = kgb3[tid]; }
        if (tid < 32) sw[WOUTo + tid] = wout[tid];
    }
    __syncthreads();

    float fq[CINc]  = {fqv.x, fqv.y, fqv.z, fqv.w};
    float fkA[CINc] = {fkAv.x, fkAv.y, fkAv.z, fkAv.w};
    float fkB[CINc] = {fkBv.x, fkBv.y, fkBv.z, fkBv.w};
    u64 gvp[DGc];
    gvp[0] = pk2(g0.x, h0.x); gvp[1] = pk2(g0.y, h0.y);
    gvp[2] = pk2(g0.z, h0.z); gvp[3] = pk2(g0.w, h0.w);
    gvp[4] = pk2(g1.x, h1.x); gvp[5] = pk2(g1.y, h1.y);
    gvp[6] = pk2(g1.z, h1.z); gvp[7] = pk2(g1.w, h1.w);
    const bool mkA = mkiA != 0;
    const bool mkB = mkiB != 0;

    float num[CINc], den[CINc];

    #pragma unroll 1
    for (int c = 0; c < CINc; ++c) {
        float kAt = 0.f, kBt = 0.f;
        u64 hp[HIDc];

        // ===== MLP_y: layer 1 (RAW pre-activations, silu deferred) =====
        {
            const float* w1 = sw + KYW1d + c * 128;
            const float* b1 = sw + KYB1d + c * 64;
            const u64 fqd = pk2(fq[c],  fq[c]);
            const u64 fkp = pk2(fkA[c], fkB[c]);
            #pragma unroll
            for (int o2 = 0; o2 < 16; ++o2) {
                ulonglong2 w0 = *reinterpret_cast<const ulonglong2*>(w1 + o2*4);
                ulonglong2 wq = *reinterpret_cast<const ulonglong2*>(w1 + 64 + o2*4);
                ulonglong2 bv = *reinterpret_cast<const ulonglong2*>(b1 + o2*4);
                hp[2*o2]   = fma2(fkp, w0.x, fma2(fqd, wq.x, bv.x));
                hp[2*o2+1] = fma2(fkp, w0.y, fma2(fqd, wq.y, bv.y));
            }
        }
        mlp23(hp, sw + KYW2t + c * 1024, sw + KYB2o + c * HIDc,
              sw + KYW3o + c * HIDc, sw[KYB3o + c], kAt, kBt);

        // ===== MLP_g: layer 1 (RAW pre-activations) =====
        {
            const float* w1 = sw + KGW1d + c * 512;
            const float* b1 = sw + KGB1d + c * 64;
            #pragma unroll
            for (int o2 = 0; o2 < 16; ++o2) {
                ulonglong2 bv = *reinterpret_cast<const ulonglong2*>(b1 + o2*4);
                hp[2*o2] = bv.x; hp[2*o2+1] = bv.y;
            }
            #pragma unroll
            for (int k = 0; k < DGc; ++k) {
                const u64 gk = gvp[k];
                const float* wk = w1 + k * 64;
                #pragma unroll
                for (int o2 = 0; o2 < 16; ++o2) {
                    ulonglong2 wv = *reinterpret_cast<const ulonglong2*>(wk + o2*4);
                    hp[2*o2]   = fma2(gk, wv.x, hp[2*o2]);
                    hp[2*o2+1] = fma2(gk, wv.y, hp[2*o2+1]);
                }
            }
        }
        mlp23(hp, sw + KGW2t + c * 1024, sw + KGB2o + c * HIDc,
              sw + KGW3o + c * HIDc, sw[KGB3o + c], kAt, kBt);

        const float eA = mkA ? ex2f(LOG2E * kAt) : 0.0f;
        const float eB = mkB ? ex2f(LOG2E * kBt) : 0.0f;
        den[c] = eA + eB;
        num[c] = fmaf(eA, fkA[c], eB * fkB[c]);
    }

    // ---- reduce over 256 threads (8 warps) ----
    #pragma unroll
    for (int c = 0; c < CINc; ++c) {
        #pragma unroll
        for (int off = 16; off > 0; off >>= 1) {
            num[c] += __shfl_xor_sync(0xFFFFFFFFu, num[c], off);
            den[c] += __shfl_xor_sync(0xFFFFFFFFu, den[c], off);
        }
    }
    const int wid = tid >> 5;
    const int lid = tid & 31;
    if (lid == 0) {
        #pragma unroll
        for (int c = 0; c < CINc; ++c) {
            sw[SREDo + wid * 8 + c]     = num[c];
            sw[SREDo + wid * 8 + 4 + c] = den[c];
        }
    }
    __syncthreads();

    if (tid < COUTc) {
        const int o = tid;
        const float mq = (mask[((size_t)b * Nc + i) * Sc + s] != 0) ? 1.0f : 0.0f;
        float acc = 0.0f;
        #pragma unroll
        for (int c = 0; c < CINc; ++c) {
            float n = 0.0f, d = 0.0f;
            #pragma unroll
            for (int w = 0; w < 8; ++w) {
                n += sw[SREDo + w * 8 + c];
                d += sw[SREDo + w * 8 + 4 + c];
            }
            const float cf = (fq[c] + n / d) * mq;
            acc = fmaf(cf, sw[WOUTo + o * CINc + c], acc);
        }
        out[(((size_t)b * Nc + i) * Sc + s) * COUTc + o] = acc;
    }
}

extern "C" void kernel_launch(void* const* d_in, const int* in_sizes, int n_in,
                              void* d_out, int out_size)
{
    const float* g    = (const float*)d_in[0];
    const float* f    = (const float*)d_in[1];
    const int*   mask = (const int*)d_in[2];
    const float* kyW1 = (const float*)d_in[3];
    const float* kyb1 = (const float*)d_in[4];
    const float* kyW2 = (const float*)d_in[5];
    const float* kyb2 = (const float*)d_in[6];
    const float* kyW3 = (const float*)d_in[7];
    const float* kyb3 = (const float*)d_in[8];
    const float* kgW1 = (const float*)d_in[9];
    const float* kgb1 = (const float*)d_in[10];
    const float* kgW2 = (const float*)d_in[11];
    const float* kgb2 = (const float*)d_in[12];
    const float* kgW3 = (const float*)d_in[13];
    const float* kgb3 = (const float*)d_in[14];
    const float* wout = (const float*)d_in[15];
    float* out = (float*)d_out;

    cudaFuncSetAttribute(ema_kernel, cudaFuncAttributeMaxDynamicSharedMemorySize, SMEM_BYTES);
    ema_kernel<<<Bc * Nc * Sc, 256, SMEM_BYTES>>>(g, f, mask,
                                      kyW1, kyb1, kyW2, kyb2, kyW3, kyb3,
                                      kgW1, kgb1, kgW2, kgb2, kgW3, kgb3,
                                      wout, out);
}

// round 7
// speedup vs baseline: 1.3850x; 1.3850x over previous
#include <cuda_runtime.h>
#include <cstdint>

// Problem constants
#define Bc    2
#define Nc    128
#define Sc    4
#define DGc   8
#define CINc  4
#define COUTc 8
#define HIDc  32

// Dynamic smem layout (float offsets).
// Layer-1 weights/biases: lane-DUPLICATED, input-major  [c][k][o][2]
// Layer-2 weights:        NON-dup, input-major          [c][k][o]
// Layer-2 bias, layer-3 w: NON-dup natural              [c][o]
#define KYW1d 0        // 512
#define KGW1d 512      // 2048
#define KYB1d 2560     // 256
#define KGB1d 2816     // 256
#define KYW2t 3072     // 4096
#define KGW2t 7168     // 4096
#define KYB2o 11264    // 128
#define KGB2o 11392    // 128
#define KYW3o 11520    // 128
#define KGW3o 11648    // 128
#define KYB3o 11776    // 4
#define KGB3o 11780    // 4
#define WOUTo 11784    // 32
#define SREDo 11816    // 64
#define SWTOT 11880
#define SMEM_BYTES (SWTOT * 4)

typedef unsigned long long u64;

__device__ __forceinline__ u64 pk2(float lo, float hi) {
    u64 r; asm("mov.b64 %0, {%1, %2};" : "=l"(r) : "f"(lo), "f"(hi)); return r;
}
__device__ __forceinline__ void upk2(u64 v, float& lo, float& hi) {
    asm("mov.b64 {%0, %1}, %2;" : "=f"(lo), "=f"(hi) : "l"(v));
}
__device__ __forceinline__ u64 fma2(u64 a, u64 b, u64 c) {
    u64 d; asm("fma.rn.f32x2 %0, %1, %2, %3;" : "=l"(d) : "l"(a), "l"(b), "l"(c)); return d;
}
__device__ __forceinline__ u64 mul2(u64 a, u64 b) {
    u64 d; asm("mul.rn.f32x2 %0, %1, %2;" : "=l"(d) : "l"(a), "l"(b)); return d;
}
__device__ __forceinline__ u64 add2(u64 a, u64 b) {
    u64 d; asm("add.rn.f32x2 %0, %1, %2;" : "=l"(d) : "l"(a), "l"(b)); return d;
}
__device__ __forceinline__ float ex2f(float x) {
    float r; asm("ex2.approx.f32 %0, %1;" : "=f"(r) : "f"(x)); return r;
}
__device__ __forceinline__ float tanhf_a(float x) {
    float r; asm("tanh.approx.f32 %0, %1;" : "=f"(r) : "f"(x)); return r;
}

#define LOG2E 1.4426950408889634f

// silu(x) = 0.5x + 0.5x * tanh(0.5x)   — 2 fma-pipe ops + 2 MUFU per pair
__device__ __forceinline__ u64 silu2(u64 x2) {
    u64 xh = mul2(x2, pk2(0.5f, 0.5f));
    float a, b; upk2(xh, a, b);
    u64 tp = pk2(tanhf_a(a), tanhf_a(b));
    return fma2(xh, tp, xh);
}
__device__ __forceinline__ float silu_f(float x) {
    float xh = 0.5f * x;
    return fmaf(xh, tanhf_a(xh), xh);
}

// Fused layers 2+3. hp[] holds post-silu activations (position-packed).
__device__ __forceinline__ void mlp23(const u64* hp,
                                      const float* __restrict__ w2,
                                      const float* __restrict__ b2,
                                      const float* __restrict__ w3,
                                      float b3, float& kA, float& kB)
{
    u64 tA0 = pk2(0.f, 0.f), tA1 = pk2(0.f, 0.f);
    u64 tB0 = pk2(0.f, 0.f), tB1 = pk2(0.f, 0.f);

    #pragma unroll 1
    for (int ch = 0; ch < 2; ++ch) {
        u64 aA[8], aB[8];
        {
            const ulonglong2* bb = reinterpret_cast<const ulonglong2*>(b2 + ch*16);
            ulonglong2 b0 = bb[0], b1v = bb[1], b2v = bb[2], b3v = bb[3];
            aA[0]=b0.x;  aA[1]=b0.y;  aA[2]=b1v.x; aA[3]=b1v.y;
            aA[4]=b2v.x; aA[5]=b2v.y; aA[6]=b3v.x; aA[7]=b3v.y;
            aB[0]=b0.x;  aB[1]=b0.y;  aB[2]=b1v.x; aB[3]=b1v.y;
            aB[4]=b2v.x; aB[5]=b2v.y; aB[6]=b3v.x; aB[7]=b3v.y;
        }
        const float* wkb = w2 + ch*16;
        #pragma unroll
        for (int k = 0; k < HIDc; ++k) {
            float ha, hb; upk2(hp[k], ha, hb);
            const u64 hAd = pk2(ha, ha);
            const u64 hBd = pk2(hb, hb);
            const ulonglong2* wv = reinterpret_cast<const ulonglong2*>(wkb + k*32);
            ulonglong2 w0 = wv[0], w1v = wv[1], w2v = wv[2], w3v = wv[3];
            aA[0] = fma2(hAd, w0.x,  aA[0]);
            aA[1] = fma2(hAd, w0.y,  aA[1]);
            aA[2] = fma2(hAd, w1v.x, aA[2]);
            aA[3] = fma2(hAd, w1v.y, aA[3]);
            aA[4] = fma2(hAd, w2v.x, aA[4]);
            aA[5] = fma2(hAd, w2v.y, aA[5]);
            aA[6] = fma2(hAd, w3v.x, aA[6]);
            aA[7] = fma2(hAd, w3v.y, aA[7]);
            aB[0] = fma2(hBd, w0.x,  aB[0]);
            aB[1] = fma2(hBd, w0.y,  aB[1]);
            aB[2] = fma2(hBd, w1v.x, aB[2]);
            aB[3] = fma2(hBd, w1v.y, aB[3]);
            aB[4] = fma2(hBd, w2v.x, aB[4]);
            aB[5] = fma2(hBd, w2v.y, aB[5]);
            aB[6] = fma2(hBd, w3v.x, aB[6]);
            aB[7] = fma2(hBd, w3v.y, aB[7]);
        }
        // silu + fold into layer-3 dot; 4 independent chains
        const ulonglong2* w3p = reinterpret_cast<const ulonglong2*>(w3 + ch*16);
        ulonglong2 p0 = w3p[0], p1 = w3p[1], p2 = w3p[2], p3 = w3p[3];
        tA0 = fma2(silu2(aA[0]), p0.x, tA0);
        tB0 = fma2(silu2(aB[0]), p0.x, tB0);
        tA1 = fma2(silu2(aA[1]), p0.y, tA1);
        tB1 = fma2(silu2(aB[1]), p0.y, tB1);
        tA0 = fma2(silu2(aA[2]), p1.x, tA0);
        tB0 = fma2(silu2(aB[2]), p1.x, tB0);
        tA1 = fma2(silu2(aA[3]), p1.y, tA1);
        tB1 = fma2(silu2(aB[3]), p1.y, tB1);
        tA0 = fma2(silu2(aA[4]), p2.x, tA0);
        tB0 = fma2(silu2(aB[4]), p2.x, tB0);
        tA1 = fma2(silu2(aA[5]), p2.y, tA1);
        tB1 = fma2(silu2(aB[5]), p2.y, tB1);
        tA0 = fma2(silu2(aA[6]), p3.x, tA0);
        tB0 = fma2(silu2(aB[6]), p3.x, tB0);
        tA1 = fma2(silu2(aA[7]), p3.y, tA1);
        tB1 = fma2(silu2(aB[7]), p3.y, tB1);
    }
    float a0, a1, b0, b1v;
    upk2(add2(tA0, tA1), a0, a1);
    upk2(add2(tB0, tB1), b0, b1v);
    kA += silu_f(a0 + a1 + b3);
    kB += silu_f(b0 + b1v + b3);
}

__global__ __launch_bounds__(256, 2)
void ema_kernel(const float* __restrict__ g,
                const float* __restrict__ f,
                const int* __restrict__ mask,
                const float* __restrict__ kyW1, const float* __restrict__ kyb1,
                const float* __restrict__ kyW2, const float* __restrict__ kyb2,
                const float* __restrict__ kyW3, const float* __restrict__ kyb3,
                const float* __restrict__ kgW1, const float* __restrict__ kgb1,
                const float* __restrict__ kgW2, const float* __restrict__ kgb2,
                const float* __restrict__ kgW3, const float* __restrict__ kgb3,
                const float* __restrict__ wout,
                float* __restrict__ out)
{
    extern __shared__ __align__(16) float sw[];

    const int tid = threadIdx.x;

    // ---- stage weights ----
    {
        for (int idx = tid; idx < 4096; idx += 256) {
            int c = idx >> 10, o = (idx >> 5) & 31, k = idx & 31;
            int d = c * 1024 + k * 32 + o;
            sw[KYW2t + d] = kyW2[idx];
            sw[KGW2t + d] = kgW2[idx];
        }
        for (int idx = tid; idx < 1024; idx += 256) {
            int c = idx >> 8, o = (idx >> 3) & 31, k = idx & 7;
            int d = ((c * 8 + k) * 32 + o) * 2;
            float v = kgW1[idx];
            sw[KGW1d + d] = v; sw[KGW1d + d + 1] = v;
        }
        if (tid < 256) {
            int idx = tid;
            int c = idx >> 6, o = (idx >> 1) & 31, k = idx & 1;
            int d = ((c * 2 + k) * 32 + o) * 2;
            float v = kyW1[idx];
            sw[KYW1d + d] = v; sw[KYW1d + d + 1] = v;
        }
        for (int idx = tid; idx < 128; idx += 256) {
            float v;
            v = kyb1[idx]; sw[KYB1d + 2*idx] = v; sw[KYB1d + 2*idx + 1] = v;
            v = kgb1[idx]; sw[KGB1d + 2*idx] = v; sw[KGB1d + 2*idx + 1] = v;
            sw[KYB2o + idx] = kyb2[idx];
            sw[KGB2o + idx] = kgb2[idx];
            sw[KYW3o + idx] = kyW3[idx];
            sw[KGW3o + idx] = kgW3[idx];
        }
        if (tid < 4) { sw[KYB3o + tid] = kyb3[tid]; sw[KGB3o + tid] = kgb3[tid]; }
        if (tid < 32) sw[WOUTo + tid] = wout[tid];
    }
    __syncthreads();

    // ---- decode query (b, i, s) ----
    const int bid = blockIdx.x;
    const int b   = bid >> 9;
    const int rem = bid & 511;
    const int i   = rem >> 2;
    const int s   = rem & 3;

    float fq[CINc];
    {
        const float* fqp = f + (((size_t)b * Nc + i) * Sc + s) * CINc;
        float4 v = *reinterpret_cast<const float4*>(fqp);
        fq[0] = v.x; fq[1] = v.y; fq[2] = v.z; fq[3] = v.w;
    }

    // ---- two keys per thread: lanes = (A,B) = (j0,t), (j0+64,t) ----
    const int j0 = tid >> 2;
    const int t  = tid & 3;
    const int j1 = j0 + 64;

    u64 gvp[DGc];
    {
        const float* gp = g + ((((((size_t)b * Nc + i) * Nc + j0) * Sc + s) * Sc) + t) * DGc;
        float4 g0 = *reinterpret_cast<const float4*>(gp);
        float4 g1 = *reinterpret_cast<const float4*>(gp + 4);
        const float* gp2 = gp + (size_t)64 * Sc * Sc * DGc;
        float4 h0 = *reinterpret_cast<const float4*>(gp2);
        float4 h1 = *reinterpret_cast<const float4*>(gp2 + 4);
        gvp[0] = pk2(g0.x, h0.x); gvp[1] = pk2(g0.y, h0.y);
        gvp[2] = pk2(g0.z, h0.z); gvp[3] = pk2(g0.w, h0.w);
        gvp[4] = pk2(g1.x, h1.x); gvp[5] = pk2(g1.y, h1.y);
        gvp[6] = pk2(g1.z, h1.z); gvp[7] = pk2(g1.w, h1.w);
    }

    const bool mkA = mask[((size_t)b * Nc + j0) * Sc + t] != 0;
    const bool mkB = mask[((size_t)b * Nc + j1) * Sc + t] != 0;

    float fkA[CINc], fkB[CINc];
    {
        const float* p0 = f + (((size_t)b * Nc + j0) * Sc + t) * CINc;
        float4 v = *reinterpret_cast<const float4*>(p0);
        fkA[0]=v.x; fkA[1]=v.y; fkA[2]=v.z; fkA[3]=v.w;
        const float* p1 = f + (((size_t)b * Nc + j1) * Sc + t) * CINc;
        float4 w = *reinterpret_cast<const float4*>(p1);
        fkB[0]=w.x; fkB[1]=w.y; fkB[2]=w.z; fkB[3]=w.w;
    }

    float num[CINc], den[CINc];

    #pragma unroll 1
    for (int c = 0; c < CINc; ++c) {
        float kAt = 0.f, kBt = 0.f;
        u64 hp[HIDc];   // position-packed activations

        #pragma unroll 1
        for (int m = 0; m < 2; ++m) {
            // ================= layer 1 (position-packed, dup weights) ====
            if (m == 0) {
                const float* w1 = sw + KYW1d + c * 128;   // [k2][o][2]
                const float* b1 = sw + KYB1d + c * 64;
                const u64 fqd = pk2(fq[c],  fq[c]);
                const u64 fkp = pk2(fkA[c], fkB[c]);
                #pragma unroll
                for (int o2 = 0; o2 < 16; ++o2) {
                    ulonglong2 w0 = *reinterpret_cast<const ulonglong2*>(w1 + o2*4);        // k=0 (key)
                    ulonglong2 wq = *reinterpret_cast<const ulonglong2*>(w1 + 64 + o2*4);   // k=1 (query)
                    ulonglong2 bv = *reinterpret_cast<const ulonglong2*>(b1 + o2*4);
                    hp[2*o2]   = silu2(fma2(fkp, w0.x, fma2(fqd, wq.x, bv.x)));
                    hp[2*o2+1] = silu2(fma2(fkp, w0.y, fma2(fqd, wq.y, bv.y)));
                }
            } else {
                const float* w1 = sw + KGW1d + c * 512;   // [k8][o][2]
                const float* b1 = sw + KGB1d + c * 64;
                #pragma unroll
                for (int o2 = 0; o2 < 16; ++o2) {
                    ulonglong2 bv = *reinterpret_cast<const ulonglong2*>(b1 + o2*4);
                    hp[2*o2] = bv.x; hp[2*o2+1] = bv.y;
                }
                #pragma unroll
                for (int k = 0; k < DGc; ++k) {
                    const u64 gk = gvp[k];
                    const float* wk = w1 + k * 64;
                    #pragma unroll
                    for (int o2 = 0; o2 < 16; ++o2) {
                        ulonglong2 wv = *reinterpret_cast<const ulonglong2*>(wk + o2*4);
                        hp[2*o2]   = fma2(gk, wv.x, hp[2*o2]);
                        hp[2*o2+1] = fma2(gk, wv.y, hp[2*o2+1]);
                    }
                }
                #pragma unroll
                for (int o = 0; o < HIDc; ++o) hp[o] = silu2(hp[o]);
            }

            // ====== fused layer 2 + 3 (output-packed, non-dup weights) ===
            mlp23(hp,
                  sw + (m ? KGW2t : KYW2t) + c * 1024,
                  sw + (m ? KGB2o : KYB2o) + c * HIDc,
                  sw + (m ? KGW3o : KYW3o) + c * HIDc,
                  sw[(m ? KGB3o : KYB3o) + c], kAt, kBt);
        }

        const float eA = mkA ? ex2f(LOG2E * kAt) : 0.0f;
        const float eB = mkB ? ex2f(LOG2E * kBt) : 0.0f;
        den[c] = eA + eB;
        num[c] = fmaf(eA, fkA[c], eB * fkB[c]);
    }

    // ---- reduce over 256 threads (8 warps) ----
    #pragma unroll
    for (int c = 0; c < CINc; ++c) {
        #pragma unroll
        for (int off = 16; off > 0; off >>= 1) {
            num[c] += __shfl_xor_sync(0xFFFFFFFFu, num[c], off);
            den[c] += __shfl_xor_sync(0xFFFFFFFFu, den[c], off);
        }
    }
    const int wid = tid >> 5;
    const int lid = tid & 31;
    if (lid == 0) {
        #pragma unroll
        for (int c = 0; c < CINc; ++c) {
            sw[SREDo + wid * 8 + c]     = num[c];
            sw[SREDo + wid * 8 + 4 + c] = den[c];
        }
    }
    __syncthreads();

    if (tid < COUTc) {
        const int o = tid;
        const float mq = (mask[((size_t)b * Nc + i) * Sc + s] != 0) ? 1.0f : 0.0f;
        float acc = 0.0f;
        #pragma unroll
        for (int c = 0; c < CINc; ++c) {
            float n = 0.0f, d = 0.0f;
            #pragma unroll
            for (int w = 0; w < 8; ++w) {
                n += sw[SREDo + w * 8 + c];
                d += sw[SREDo + w * 8 + 4 + c];
            }
            const float cf = (fq[c] + n / d) * mq;
            acc = fmaf(cf, sw[WOUTo + o * CINc + c], acc);
        }
        out[(((size_t)b * Nc + i) * Sc + s) * COUTc + o] = acc;
    }
}

extern "C" void kernel_launch(void* const* d_in, const int* in_sizes, int n_in,
                              void* d_out, int out_size)
{
    const float* g    = (const float*)d_in[0];
    const float* f    = (const float*)d_in[1];
    const int*   mask = (const int*)d_in[2];
    const float* kyW1 = (const float*)d_in[3];
    const float* kyb1 = (const float*)d_in[4];
    const float* kyW2 = (const float*)d_in[5];
    const float* kyb2 = (const float*)d_in[6];
    const float* kyW3 = (const float*)d_in[7];
    const float* kyb3 = (const float*)d_in[8];
    const float* kgW1 = (const float*)d_in[9];
    const float* kgb1 = (const float*)d_in[10];
    const float* kgW2 = (const float*)d_in[11];
    const float* kgb2 = (const float*)d_in[12];
    const float* kgW3 = (const float*)d_in[13];
    const float* kgb3 = (const float*)d_in[14];
    const float* wout = (const float*)d_in[15];
    float* out = (float*)d_out;

    cudaFuncSetAttribute(ema_kernel, cudaFuncAttributeMaxDynamicSharedMemorySize, SMEM_BYTES);
    ema_kernel<<<Bc * Nc * Sc, 256, SMEM_BYTES>>>(g, f, mask,
                                      kyW1, kyb1, kyW2, kyb2, kyW3, kyb3,
                                      kgW1, kgb1, kgW2, kgb2, kgW3, kgb3,
                                      wout, out);
}